// round 1
// baseline (speedup 1.0000x reference)
#include <cuda_runtime.h>

// Problem constants
#define NPTS   32768      // B*H*W
#define KCODES 1024
#define DDIM   256
#define HWSZ   1024       // H*W
#define HALF_OUT 8388608  // B*D*H*W

// Scratch (no allocations allowed)
__device__ float g_xx[NPTS];
__device__ float g_cc[KCODES];
__device__ int   g_idx[NPTS];

// ---------------------------------------------------------------------------
// cc[k] = sequential sum of fl(c*c) over d (mimics eager jnp: square rounded,
// then unreassociated sequential reduce). No FMA contraction.
// ---------------------------------------------------------------------------
__global__ void cc_kernel(const float* __restrict__ cb) {
    int k = blockIdx.x * blockDim.x + threadIdx.x;
    if (k >= KCODES) return;
    const float* row = cb + (size_t)k * DDIM;
    float s = 0.0f;
    for (int d = 0; d < DDIM; ++d) {
        float v = row[d];
        s = __fadd_rn(s, __fmul_rn(v, v));
    }
    g_cc[k] = s;
}

// ---------------------------------------------------------------------------
// xx[n] = sequential sum of fl(x*x) over d. z_e_x layout [B, D, H, W]:
// point n = (b, hw) reads stride HW in d -> fully coalesced across the warp.
// ---------------------------------------------------------------------------
__global__ void xx_kernel(const float* __restrict__ z) {
    int n = blockIdx.x * blockDim.x + threadIdx.x;
    if (n >= NPTS) return;
    int b = n >> 10, hw = n & 1023;
    const float* base = z + (size_t)b * DDIM * HWSZ + hw;
    float s = 0.0f;
    for (int d = 0; d < DDIM; ++d) {
        float v = base[(size_t)d * HWSZ];
        s = __fadd_rn(s, __fmul_rn(v, v));
    }
    g_xx[n] = s;
}

// ---------------------------------------------------------------------------
// Main kernel: 128-point x 128-code register-blocked fp32 GEMM tiles with a
// running per-point argmin across all K=1024 codes (8 code tiles per block).
// Each output dot is ONE sequential fp32 FMA chain over d=0..255 (Eigen gebp
// order). Distance applied as d = fl(fl(xx+cc) - 2m). Ties -> smallest index.
// 256 threads: tx = code-group (16 x 8 codes), ty = point-group (16 x 8 pts).
// ---------------------------------------------------------------------------
__global__ __launch_bounds__(256, 2)
void argmin_kernel(const float* __restrict__ z, const float* __restrict__ cb) {
    __shared__ __align__(16) float As[16][128];   // [dk][point]
    __shared__ float Bs[16][132];                 // [dk][code], padded
    __shared__ float rV[128][16];
    __shared__ int   rI[128][16];

    const int tid = threadIdx.x;
    const int tx = tid & 15;       // code group
    const int ty = tid >> 4;       // point group
    const int p0 = blockIdx.x * 128;
    const int b = p0 >> 10;
    const int hw0 = p0 & 1023;
    const float* zbase = z + (size_t)b * DDIM * HWSZ + hw0;

    float bestV[8];
    int   bestK[8];
    #pragma unroll
    for (int i = 0; i < 8; ++i) { bestV[i] = 3.0e38f; bestK[i] = 0; }

    float xxr[8];
    #pragma unroll
    for (int i = 0; i < 8; ++i) xxr[i] = g_xx[p0 + ty * 8 + i];

    for (int k0 = 0; k0 < KCODES; k0 += 128) {
        float acc[8][8];
        #pragma unroll
        for (int i = 0; i < 8; ++i)
            #pragma unroll
            for (int j = 0; j < 8; ++j) acc[i][j] = 0.0f;

        for (int d0 = 0; d0 < DDIM; d0 += 16) {
            __syncthreads();
            // Load x tile: As[dk][p] = z[b, d0+dk, hw0+p]  (float4, coalesced)
            #pragma unroll
            for (int h = 0; h < 2; ++h) {
                int lin = tid + h * 256;          // 0..511
                int dk = lin >> 5;                // 0..15
                int c4 = (lin & 31) << 2;         // 0,4,...,124
                float4 v = *reinterpret_cast<const float4*>(
                    zbase + (size_t)(d0 + dk) * HWSZ + c4);
                *reinterpret_cast<float4*>(&As[dk][c4]) = v;
            }
            // Load codebook tile transposed: Bs[dk][kk] = cb[k0+kk][d0+dk]
            #pragma unroll
            for (int h = 0; h < 2; ++h) {
                int lin = tid + h * 256;          // 0..511
                int kk = lin >> 2;                // 0..127
                int q  = (lin & 3) << 2;          // 0,4,8,12
                float4 v = *reinterpret_cast<const float4*>(
                    cb + (size_t)(k0 + kk) * DDIM + d0 + q);
                Bs[q + 0][kk] = v.x;
                Bs[q + 1][kk] = v.y;
                Bs[q + 2][kk] = v.z;
                Bs[q + 3][kk] = v.w;
            }
            __syncthreads();

            #pragma unroll
            for (int dk = 0; dk < 16; ++dk) {
                float a[8], bb[8];
                #pragma unroll
                for (int i = 0; i < 8; ++i) a[i] = As[dk][ty * 8 + i];
                #pragma unroll
                for (int j = 0; j < 8; ++j) bb[j] = Bs[dk][tx * 8 + j];
                #pragma unroll
                for (int i = 0; i < 8; ++i)
                    #pragma unroll
                    for (int j = 0; j < 8; ++j)
                        acc[i][j] = __fmaf_rn(a[i], bb[j], acc[i][j]);
            }
        }

        // Epilogue: distance + running argmin for this code tile
        #pragma unroll
        for (int j = 0; j < 8; ++j) {
            int k = k0 + tx * 8 + j;
            float cck = g_cc[k];
            #pragma unroll
            for (int i = 0; i < 8; ++i) {
                float t1   = __fadd_rn(xxr[i], cck);           // fl(xx + cc)
                float twom = 2.0f * acc[i][j];                 // exact
                float dd   = __fadd_rn(t1, -twom);             // fl(t1 - 2m)
                if (dd < bestV[i] || (dd == bestV[i] && k < bestK[i])) {
                    bestV[i] = dd;
                    bestK[i] = k;
                }
            }
        }
    }

    // Cross-thread (tx) reduction per point, first-index tie-break
    #pragma unroll
    for (int i = 0; i < 8; ++i) {
        rV[ty * 8 + i][tx] = bestV[i];
        rI[ty * 8 + i][tx] = bestK[i];
    }
    __syncthreads();
    if (tid < 128) {
        float bv = rV[tid][0];
        int   bk = rI[tid][0];
        #pragma unroll
        for (int t = 1; t < 16; ++t) {
            float v = rV[tid][t];
            int   k = rI[tid][t];
            if (v < bv || (v == bv && k < bk)) { bv = v; bk = k; }
        }
        g_idx[p0 + tid] = bk;
    }
}

// ---------------------------------------------------------------------------
// Gather + straight-through outputs. Flat index i over [B, D, H, W] matches
// z_e_x layout exactly. z_q_x = fl(x + fl(q - x)); zqx_tilde = q.
// Writes coalesced (hw contiguous); codebook gathers hit L2 (1 MB resident).
// ---------------------------------------------------------------------------
__global__ void gather_kernel(const float* __restrict__ z,
                              const float* __restrict__ cb,
                              float* __restrict__ out) {
    int i = blockIdx.x * blockDim.x + threadIdx.x;
    if (i >= HALF_OUT) return;
    int hw = i & 1023;
    int d  = (i >> 10) & 255;
    int b  = i >> 18;
    int n  = (b << 10) | hw;
    int k  = g_idx[n];
    float q = cb[(size_t)k * DDIM + d];
    float x = z[i];
    float t = __fadd_rn(q, -x);        // fl(q - x)
    out[i]            = __fadd_rn(x, t); // z_q_x
    out[i + HALF_OUT] = q;               // zqx_tilde
}

// ---------------------------------------------------------------------------
extern "C" void kernel_launch(void* const* d_in, const int* in_sizes, int n_in,
                              void* d_out, int out_size) {
    const float* z  = (const float*)d_in[0];   // z_e_x  [32,256,32,32]
    const float* cb = (const float*)d_in[1];   // codebook [1024,256]
    float* out = (float*)d_out;                // [2, 32,256,32,32]

    cc_kernel<<<(KCODES + 255) / 256, 256>>>(cb);
    xx_kernel<<<(NPTS + 255) / 256, 256>>>(z);
    argmin_kernel<<<NPTS / 128, 256>>>(z, cb);
    gather_kernel<<<(HALF_OUT + 255) / 256, 256>>>(z, cb, out);
}

// round 2
// speedup vs baseline: 1.7714x; 1.7714x over previous
#include <cuda_runtime.h>

// Problem constants
#define NPTS   32768      // B*H*W
#define KCODES 1024
#define DDIM   256
#define HWSZ   1024       // H*W
#define HALF_OUT 8388608  // B*D*H*W

typedef unsigned long long u64;

// Scratch (no allocations allowed)
__device__ float g_xx[NPTS];
__device__ float g_cc[KCODES];
__device__ int   g_idx[NPTS];

// Packed fp32x2 FMA: two independent fp32 FMA chains per instruction.
// Each lane rounds identically to scalar __fmaf_rn -> bitwise-preserving.
__device__ __forceinline__ u64 ffma2(u64 a, u64 b, u64 c) {
    u64 d;
    asm("fma.rn.f32x2 %0, %1, %2, %3;" : "=l"(d) : "l"(a), "l"(b), "l"(c));
    return d;
}
__device__ __forceinline__ u64 packf2(float lo, float hi) {
    u64 d; asm("mov.b64 %0, {%1, %2};" : "=l"(d) : "f"(lo), "f"(hi)); return d;
}
__device__ __forceinline__ void unpackf2(u64 v, float& lo, float& hi) {
    asm("mov.b64 {%0, %1}, %2;" : "=f"(lo), "=f"(hi) : "l"(v));
}

// ---------------------------------------------------------------------------
// cc[k] = sequential sum of fl(c*c) over d. (Unchanged — numerics pinned.)
// ---------------------------------------------------------------------------
__global__ void cc_kernel(const float* __restrict__ cb) {
    int k = blockIdx.x * blockDim.x + threadIdx.x;
    if (k >= KCODES) return;
    const float* row = cb + (size_t)k * DDIM;
    float s = 0.0f;
    for (int d = 0; d < DDIM; ++d) {
        float v = row[d];
        s = __fadd_rn(s, __fmul_rn(v, v));
    }
    g_cc[k] = s;
}

// ---------------------------------------------------------------------------
// xx[n] = sequential sum of fl(x*x) over d. (Unchanged — numerics pinned.)
// ---------------------------------------------------------------------------
__global__ void xx_kernel(const float* __restrict__ z) {
    int n = blockIdx.x * blockDim.x + threadIdx.x;
    if (n >= NPTS) return;
    int b = n >> 10, hw = n & 1023;
    const float* base = z + (size_t)b * DDIM * HWSZ + hw;
    float s = 0.0f;
    for (int d = 0; d < DDIM; ++d) {
        float v = base[(size_t)d * HWSZ];
        s = __fadd_rn(s, __fmul_rn(v, v));
    }
    g_xx[n] = s;
}

// ---------------------------------------------------------------------------
// Main kernel: 128-point x 128-code fp32 GEMM tiles + running argmin.
// Inner product per (point,code) remains ONE sequential fp32 FMA chain over
// d=0..255 (matches cuBLAS SGEMM accumulation -> bitwise-equal distances).
// NEW: accumulators packed pairwise over j into fma.rn.f32x2 (FFMA2) — two
// independent chains per instruction, 2x fma-pipe throughput on sm_103a
// (FFMA-3reg is half-rate; FFMA2 recovers full rate).
// ---------------------------------------------------------------------------
__global__ __launch_bounds__(256, 2)
void argmin_kernel(const float* __restrict__ z, const float* __restrict__ cb) {
    __shared__ __align__(16) float As[16][128];   // [dk][point]
    __shared__ __align__(16) float Bs[16][132];   // [dk][code], padded
    __shared__ float rV[128][16];
    __shared__ int   rI[128][16];

    const int tid = threadIdx.x;
    const int tx = tid & 15;       // code group
    const int ty = tid >> 4;       // point group
    const int p0 = blockIdx.x * 128;
    const int b = p0 >> 10;
    const int hw0 = p0 & 1023;
    const float* zbase = z + (size_t)b * DDIM * HWSZ + hw0;

    float bestV[8];
    int   bestK[8];
    #pragma unroll
    for (int i = 0; i < 8; ++i) { bestV[i] = 3.0e38f; bestK[i] = 0; }

    float xxr[8];
    #pragma unroll
    for (int i = 0; i < 8; ++i) xxr[i] = g_xx[p0 + ty * 8 + i];

    for (int k0 = 0; k0 < KCODES; k0 += 128) {
        // accp[i][jp] = (acc[i][2jp], acc[i][2jp+1]) packed fp32x2
        u64 accp[8][4];
        #pragma unroll
        for (int i = 0; i < 8; ++i)
            #pragma unroll
            for (int jp = 0; jp < 4; ++jp) accp[i][jp] = 0ull;

        for (int d0 = 0; d0 < DDIM; d0 += 16) {
            __syncthreads();
            // Load x tile: As[dk][p] = z[b, d0+dk, hw0+p]  (float4, coalesced)
            #pragma unroll
            for (int h = 0; h < 2; ++h) {
                int lin = tid + h * 256;          // 0..511
                int dk = lin >> 5;                // 0..15
                int c4 = (lin & 31) << 2;         // 0,4,...,124
                float4 v = *reinterpret_cast<const float4*>(
                    zbase + (size_t)(d0 + dk) * HWSZ + c4);
                *reinterpret_cast<float4*>(&As[dk][c4]) = v;
            }
            // Load codebook tile transposed: Bs[dk][kk] = cb[k0+kk][d0+dk]
            #pragma unroll
            for (int h = 0; h < 2; ++h) {
                int lin = tid + h * 256;          // 0..511
                int kk = lin >> 2;                // 0..127
                int q  = (lin & 3) << 2;          // 0,4,8,12
                float4 v = *reinterpret_cast<const float4*>(
                    cb + (size_t)(k0 + kk) * DDIM + d0 + q);
                Bs[q + 0][kk] = v.x;
                Bs[q + 1][kk] = v.y;
                Bs[q + 2][kk] = v.z;
                Bs[q + 3][kk] = v.w;
            }
            __syncthreads();

            #pragma unroll
            for (int dk = 0; dk < 16; ++dk) {
                // b pairs: natural contiguous float2 in Bs (8B aligned)
                u64 bp[4];
                #pragma unroll
                for (int jp = 0; jp < 4; ++jp)
                    bp[jp] = *reinterpret_cast<const u64*>(&Bs[dk][tx * 8 + jp * 2]);
                // a values: two float4 (broadcast within half-warp)
                float4 a0 = *reinterpret_cast<const float4*>(&As[dk][ty * 8]);
                float4 a1 = *reinterpret_cast<const float4*>(&As[dk][ty * 8 + 4]);
                float a[8] = {a0.x, a0.y, a0.z, a0.w, a1.x, a1.y, a1.z, a1.w};
                #pragma unroll
                for (int i = 0; i < 8; ++i) {
                    u64 ap = packf2(a[i], a[i]);
                    #pragma unroll
                    for (int jp = 0; jp < 4; ++jp)
                        accp[i][jp] = ffma2(ap, bp[jp], accp[i][jp]);
                }
            }
        }

        // Epilogue: distance + running argmin for this code tile
        #pragma unroll
        for (int jp = 0; jp < 4; ++jp) {
            int kb = k0 + tx * 8 + jp * 2;
            float cc0 = g_cc[kb];
            float cc1 = g_cc[kb + 1];
            #pragma unroll
            for (int i = 0; i < 8; ++i) {
                float m0, m1;
                unpackf2(accp[i][jp], m0, m1);
                // code kb
                {
                    float t1   = __fadd_rn(xxr[i], cc0);
                    float dd   = __fadd_rn(t1, -(2.0f * m0));
                    if (dd < bestV[i] || (dd == bestV[i] && kb < bestK[i])) {
                        bestV[i] = dd; bestK[i] = kb;
                    }
                }
                // code kb+1
                {
                    float t1   = __fadd_rn(xxr[i], cc1);
                    float dd   = __fadd_rn(t1, -(2.0f * m1));
                    int k = kb + 1;
                    if (dd < bestV[i] || (dd == bestV[i] && k < bestK[i])) {
                        bestV[i] = dd; bestK[i] = k;
                    }
                }
            }
        }
    }

    // Cross-thread (tx) reduction per point, first-index tie-break
    #pragma unroll
    for (int i = 0; i < 8; ++i) {
        rV[ty * 8 + i][tx] = bestV[i];
        rI[ty * 8 + i][tx] = bestK[i];
    }
    __syncthreads();
    if (tid < 128) {
        float bv = rV[tid][0];
        int   bk = rI[tid][0];
        #pragma unroll
        for (int t = 1; t < 16; ++t) {
            float v = rV[tid][t];
            int   k = rI[tid][t];
            if (v < bv || (v == bv && k < bk)) { bv = v; bk = k; }
        }
        g_idx[p0 + tid] = bk;
    }
}

// ---------------------------------------------------------------------------
// Gather + straight-through outputs, tiled so ALL global traffic is coalesced.
// Block = 32 points (same b, consecutive hw). Stage the 32 needed codebook
// rows in shared (padded 257 -> conflict-free reads), then stream z/out with
// 128B-coalesced rows. Math per element unchanged: z_q_x = fl(x + fl(q-x)).
// ---------------------------------------------------------------------------
#define GPTS 32
__global__ __launch_bounds__(256)
void gather_kernel(const float* __restrict__ z,
                   const float* __restrict__ cb,
                   float* __restrict__ out) {
    __shared__ float tile[GPTS][DDIM + 1];   // 257-float rows: bank = (p+d)%32
    __shared__ int sidx[GPTS];

    const int tid = threadIdx.x;
    const int p0 = blockIdx.x * GPTS;
    const int b = p0 >> 10;
    const int hw0 = p0 & 1023;

    if (tid < GPTS) sidx[tid] = g_idx[p0 + tid];
    __syncthreads();

    // Stage 32 codebook rows: 2048 float4, 256 threads -> 8 each, coalesced.
    #pragma unroll
    for (int r = 0; r < 8; ++r) {
        int lin = tid + r * 256;        // 0..2047
        int p = lin >> 6;               // 64 float4 per row
        int d4 = (lin & 63) << 2;
        float4 v = *reinterpret_cast<const float4*>(
            cb + (size_t)sidx[p] * DDIM + d4);
        tile[p][d4 + 0] = v.x;
        tile[p][d4 + 1] = v.y;
        tile[p][d4 + 2] = v.z;
        tile[p][d4 + 3] = v.w;
    }
    __syncthreads();

    const float* zb = z + (size_t)b * DDIM * HWSZ + hw0;
    float* o1 = out + (size_t)b * DDIM * HWSZ + hw0;
    const int p = tid & 31;
    const int dchunk = tid >> 5;

    #pragma unroll
    for (int dd = 0; dd < DDIM; dd += 8) {
        int d = dd + dchunk;
        size_t off = (size_t)d * HWSZ + p;
        float x = zb[off];
        float q = tile[p][d];
        float t = __fadd_rn(q, -x);          // fl(q - x)
        o1[off]            = __fadd_rn(x, t); // z_q_x
        o1[off + HALF_OUT] = q;               // zqx_tilde
    }
}

// ---------------------------------------------------------------------------
extern "C" void kernel_launch(void* const* d_in, const int* in_sizes, int n_in,
                              void* d_out, int out_size) {
    const float* z  = (const float*)d_in[0];   // z_e_x  [32,256,32,32]
    const float* cb = (const float*)d_in[1];   // codebook [1024,256]
    float* out = (float*)d_out;                // [2, 32,256,32,32]

    cc_kernel<<<(KCODES + 255) / 256, 256>>>(cb);
    xx_kernel<<<(NPTS + 255) / 256, 256>>>(z);
    argmin_kernel<<<NPTS / 128, 256>>>(z, cb);
    gather_kernel<<<NPTS / GPTS, 256>>>(z, cb, out);
}